// round 11
// baseline (speedup 1.0000x reference)
#include <cuda_runtime.h>
#include <cstdint>

#define T_STEPS 512
#define BATCH   256
#define DIN     256
#define HID     128
#define GATES   512   // 4*HID, gate order i,f,g,o

// Scratch: allocation-free rule => __device__ globals.
__device__ float g_xg[(size_t)T_STEPS * BATCH * GATES];  // x@W_ih^T + b_ih + b_hh

// ---------------- packed f32x2 helpers (FFMA2: 2 MACs/instr) ----------------
__device__ __forceinline__ unsigned long long pk2(float lo, float hi) {
    unsigned long long r; asm("mov.b64 %0, {%1, %2};" : "=l"(r) : "f"(lo), "f"(hi)); return r;
}
__device__ __forceinline__ unsigned long long dup2(float x) {
    unsigned long long r; asm("mov.b64 %0, {%1, %1};" : "=l"(r) : "f"(x)); return r;
}
__device__ __forceinline__ void up2(unsigned long long v, float& lo, float& hi) {
    asm("mov.b64 {%0, %1}, %2;" : "=f"(lo), "=f"(hi) : "l"(v));
}
__device__ __forceinline__ unsigned long long fma2(unsigned long long a, unsigned long long b,
                                                   unsigned long long c) {
    unsigned long long d;
    asm("fma.rn.f32x2 %0, %1, %2, %3;" : "=l"(d) : "l"(a), "l"(b), "l"(c));
    return d;
}
__device__ __forceinline__ float sigm_f(float x) { return 1.0f / (1.0f + __expf(-x)); }
__device__ __forceinline__ float tanh_f(float x) { return 2.0f / (1.0f + __expf(-2.0f * x)) - 1.0f; }

// ============================================================================
// Kernel 1: x_gates GEMM.  C[131072,512] = X[131072,256] @ Wih^T + (b_ih+b_hh)
// 128x128 tiles, BK=16, double-buffered smem, 8x8 micro-tile, f32x2 accums.
// ============================================================================
__global__ void __launch_bounds__(256) xg_gemm(const float* __restrict__ X,
                                               const float* __restrict__ Wih,
                                               const float* __restrict__ bih,
                                               const float* __restrict__ bhh)
{
    __shared__ __align__(16) float As[2][16][132];   // [buf][k][m], padded
    __shared__ __align__(16) float Bs[2][16][132];   // [buf][k][n], padded

    const int tid = threadIdx.x;
    const int m0  = blockIdx.y * 128;
    const int n0  = blockIdx.x * 128;
    const int tx  = tid & 15;          // n micro-tile id
    const int ty  = tid >> 4;          // m micro-tile id
    const int row = tid >> 2;          // 0..63 (load role)
    const int kq  = tid & 3;

    const float* Ap = X   + (size_t)(m0 + row) * DIN + kq * 4;
    const float* Bp = Wih + (size_t)(n0 + row) * DIN + kq * 4;

    float4 ra0 = *(const float4*)(Ap);
    float4 ra1 = *(const float4*)(Ap + 64 * DIN);
    float4 rb0 = *(const float4*)(Bp);
    float4 rb1 = *(const float4*)(Bp + 64 * DIN);

    unsigned long long acc[8][4];
#pragma unroll
    for (int i = 0; i < 8; ++i)
#pragma unroll
        for (int j = 0; j < 4; ++j) acc[i][j] = 0ULL;

    int buf = 0;
#pragma unroll 1
    for (int kt = 0; kt < 16; ++kt) {
#pragma unroll
        for (int e = 0; e < 4; ++e) {
            As[buf][kq*4+e][row]    = ((const float*)&ra0)[e];
            As[buf][kq*4+e][row+64] = ((const float*)&ra1)[e];
            Bs[buf][kq*4+e][row]    = ((const float*)&rb0)[e];
            Bs[buf][kq*4+e][row+64] = ((const float*)&rb1)[e];
        }
        __syncthreads();
        if (kt < 15) {  // stage next K-tile; LDG hidden behind compute
            ra0 = *(const float4*)(Ap + (kt+1)*16);
            ra1 = *(const float4*)(Ap + 64*DIN + (kt+1)*16);
            rb0 = *(const float4*)(Bp + (kt+1)*16);
            rb1 = *(const float4*)(Bp + 64*DIN + (kt+1)*16);
        }
#pragma unroll
        for (int k = 0; k < 16; ++k) {
            float4 a0 = *(const float4*)&As[buf][k][ty*4];
            float4 a1 = *(const float4*)&As[buf][k][64 + ty*4];
            ulonglong2 b0 = *(const ulonglong2*)&Bs[buf][k][tx*4];
            ulonglong2 b1 = *(const ulonglong2*)&Bs[buf][k][64 + tx*4];
            float am[8] = {a0.x,a0.y,a0.z,a0.w,a1.x,a1.y,a1.z,a1.w};
            unsigned long long bp[4] = {b0.x, b0.y, b1.x, b1.y};
#pragma unroll
            for (int i = 0; i < 8; ++i) {
                unsigned long long ad = dup2(am[i]);
#pragma unroll
                for (int j = 0; j < 4; ++j) acc[i][j] = fma2(ad, bp[j], acc[i][j]);
            }
        }
        buf ^= 1;
    }

    // epilogue: +(b_ih+b_hh), store
    float b_lo[4], b_hi[4];
#pragma unroll
    for (int j = 0; j < 4; ++j) {
        b_lo[j] = bih[n0 + tx*4 + j]      + bhh[n0 + tx*4 + j];
        b_hi[j] = bih[n0 + 64 + tx*4 + j] + bhh[n0 + 64 + tx*4 + j];
    }
#pragma unroll
    for (int i = 0; i < 8; ++i) {
        int m = m0 + ((i < 4) ? (ty*4 + i) : (64 + ty*4 + i - 4));
        float v[8];
        up2(acc[i][0], v[0], v[1]);
        up2(acc[i][1], v[2], v[3]);
        up2(acc[i][2], v[4], v[5]);
        up2(acc[i][3], v[6], v[7]);
        float* dst = g_xg + (size_t)m * GATES + n0;
        *(float4*)(dst + tx*4)      = make_float4(v[0]+b_lo[0], v[1]+b_lo[1], v[2]+b_lo[2], v[3]+b_lo[3]);
        *(float4*)(dst + 64 + tx*4) = make_float4(v[4]+b_hi[0], v[5]+b_hi[1], v[6]+b_hi[2], v[7]+b_hi[3]);
    }
}

// ============================================================================
// Kernel 2: LSTM recurrence + FC head.
// 64 clusters x 2 CTAs. Cluster g owns batches [4g,4g+4). CTA rank r owns
// hidden slice j in [64r,64r+64): its 4-gate W_hh rows (132KB padded fp32)
// stay RESIDENT in smem for all 512 steps. Per step: smem GEMV, gate math,
// h-half exchange to peer via DSMEM store + one cluster barrier.
// Thread map tid = jj*4 + b keeps each warp's W reads to 8 distinct 16B
// chunks (4-lane broadcast) = 128B unique/LDS -> 1 crossbar wavefront.
// ============================================================================
#define W_PAD 132
#define REC_SMEM ((4*64*W_PAD + 2*4*W_PAD) * 4)   // 139392 bytes

__global__ void __launch_bounds__(256) __cluster_dims__(2, 1, 1)
lstm_rec(const float* __restrict__ Whh, const float* __restrict__ h0,
         const float* __restrict__ c0,  const float* __restrict__ fcw,
         const float* __restrict__ fcb, float* __restrict__ out)
{
    extern __shared__ float sm[];
    float* Wsm = sm;                    // [4 gates][64 jj][W_PAD]
    float* hb  = sm + 4*64*W_PAD;       // [2 parity][4 b][W_PAD]  (full h, 128 used)

    const int tid = threadIdx.x;
    const int b   = tid & 3;            // batch-local
    const int jj  = tid >> 2;           // 0..63 output within slice
    uint32_t rank;
    asm("mov.u32 %0, %%cluster_ctarank;" : "=r"(rank));
    const uint32_t peer = rank ^ 1u;
    const int jglob = (int)rank * 64 + jj;
    const int bbase = (blockIdx.x >> 1) * 4;

    // Load resident W_hh slice: Wsm[q][jj][k] = Whh[(q*128 + rank*64 + jj)*128 + k]
#pragma unroll 1
    for (int it = 0; it < 32; ++it) {
        int idx4 = tid + it * 256;                 // over float4s, 8192 total
        int k4 = idx4 & 31;
        int j  = (idx4 >> 5) & 63;
        int q  = idx4 >> 11;
        float4 w = *(const float4*)(Whh + ((size_t)(q*128 + (int)rank*64 + j) * HID + k4*4));
        *(float4*)(Wsm + (size_t)(q*64 + j) * W_PAD + k4*4) = w;
    }
    // Init full h (parity 0) for this cluster's 4 batches
    for (int idx = tid; idx < 4*HID; idx += 256) {
        int b_ = idx >> 7, k = idx & 127;
        hb[(0*4 + b_) * W_PAD + k] = h0[(size_t)(bbase + b_) * HID + k];
    }
    float c = c0[(size_t)(bbase + b) * HID + jglob];
    __syncthreads();
    asm volatile("barrier.cluster.arrive.aligned;" ::: "memory");
    asm volatile("barrier.cluster.wait.aligned;"   ::: "memory");

    const float* xg_base = g_xg + (size_t)(bbase + b) * GATES + jglob;
    float nx0 = xg_base[0], nx1 = xg_base[128], nx2 = xg_base[256], nx3 = xg_base[384];

    int p = 0;
#pragma unroll 1
    for (int t = 0; t < T_STEPS; ++t) {
        float cg0 = nx0, cg1 = nx1, cg2 = nx2, cg3 = nx3;
        if (t + 1 < T_STEPS) {  // prefetch next step's preactivations
            const float* pn = xg_base + (size_t)(t + 1) * (BATCH * GATES);
            nx0 = pn[0]; nx1 = pn[128]; nx2 = pn[256]; nx3 = pn[384];
        }

        unsigned long long a0 = 0ULL, a1 = 0ULL, a2 = 0ULL, a3 = 0ULL;
        const float* hrow = hb + (size_t)(p*4 + b) * W_PAD;
        const float* w0 = Wsm + (size_t)(0*64 + jj) * W_PAD;
        const float* w1 = Wsm + (size_t)(1*64 + jj) * W_PAD;
        const float* w2 = Wsm + (size_t)(2*64 + jj) * W_PAD;
        const float* w3 = Wsm + (size_t)(3*64 + jj) * W_PAD;
#pragma unroll 8
        for (int k4 = 0; k4 < 32; ++k4) {
            float4 h4 = *(const float4*)(hrow + k4*4);
            unsigned long long ha = pk2(h4.x, h4.y);
            unsigned long long hc = pk2(h4.z, h4.w);
            ulonglong2 W0 = *(const ulonglong2*)(w0 + k4*4);
            ulonglong2 W1 = *(const ulonglong2*)(w1 + k4*4);
            ulonglong2 W2 = *(const ulonglong2*)(w2 + k4*4);
            ulonglong2 W3 = *(const ulonglong2*)(w3 + k4*4);
            a0 = fma2(ha, W0.x, a0); a0 = fma2(hc, W0.y, a0);
            a1 = fma2(ha, W1.x, a1); a1 = fma2(hc, W1.y, a1);
            a2 = fma2(ha, W2.x, a2); a2 = fma2(hc, W2.y, a2);
            a3 = fma2(ha, W3.x, a3); a3 = fma2(hc, W3.y, a3);
        }
        float lo, hi, gi, gf, gg, go;
        up2(a0, lo, hi); gi = cg0 + lo + hi;
        up2(a1, lo, hi); gf = cg1 + lo + hi;
        up2(a2, lo, hi); gg = cg2 + lo + hi;
        up2(a3, lo, hi); go = cg3 + lo + hi;

        float ig = sigm_f(gi), fg = sigm_f(gf), gt = tanh_f(gg), og = sigm_f(go);
        c = fg * c + ig * gt;
        float h = og * tanh_f(c);

        // publish h to both CTAs' hb[p^1]
        float* dst = hb + (size_t)((p ^ 1) * 4 + b) * W_PAD + jglob;
        *dst = h;
        uint32_t laddr = (uint32_t)__cvta_generic_to_shared(dst);
        uint32_t raddr;
        asm volatile("mapa.shared::cluster.u32 %0, %1, %2;" : "=r"(raddr) : "r"(laddr), "r"(peer));
        asm volatile("st.shared::cluster.f32 [%0], %1;" :: "r"(raddr), "f"(h) : "memory");

        asm volatile("barrier.cluster.arrive.aligned;" ::: "memory");
        asm volatile("barrier.cluster.wait.aligned;"   ::: "memory");
        p ^= 1;
    }

    // FC head on final h: warp 0 (rank 0) does 4 batches, one warp-parallel
    // dot product each (32 lanes x 4 values + shfl reduce).
    if (rank == 0 && tid < 32) {
        const int lane = tid;
        for (int b_ = 0; b_ < 4; ++b_) {
            const float* hr = hb + (size_t)(p*4 + b_) * W_PAD;
            float acc = 0.0f;
#pragma unroll
            for (int kk = 0; kk < 4; ++kk) {
                int k = lane + kk * 32;
                acc += hr[k] * fcw[k];
            }
#pragma unroll
            for (int off = 16; off > 0; off >>= 1)
                acc += __shfl_xor_sync(0xFFFFFFFFu, acc, off);
            if (lane == 0) out[bbase + b_] = acc + fcb[0];
        }
    }
}

// ============================================================================
extern "C" void kernel_launch(void* const* d_in, const int* in_sizes, int n_in,
                              void* d_out, int out_size) {
    const float* x   = (const float*)d_in[0];
    const float* h0  = (const float*)d_in[1];
    const float* c0  = (const float*)d_in[2];
    const float* Wih = (const float*)d_in[3];
    const float* Whh = (const float*)d_in[4];
    const float* bih = (const float*)d_in[5];
    const float* bhh = (const float*)d_in[6];
    const float* fcw = (const float*)d_in[7];
    const float* fcb = (const float*)d_in[8];
    float* out = (float*)d_out;
    (void)in_sizes; (void)n_in; (void)out_size;

    // Unconditional (idempotent; no static guards allowed by harness rules).
    cudaFuncSetAttribute(lstm_rec, cudaFuncAttributeMaxDynamicSharedMemorySize, REC_SMEM);

    dim3 g1(GATES / 128, (T_STEPS * BATCH) / 128);   // (4, 1024)
    xg_gemm<<<g1, 256>>>(x, Wih, bih, bhh);
    lstm_rec<<<128, 256, REC_SMEM>>>(Whh, h0, c0, fcw, fcb, out);
}

// round 12
// speedup vs baseline: 1.1103x; 1.1103x over previous
#include <cuda_runtime.h>
#include <cstdint>

#define T_STEPS 512
#define BATCH   256
#define DIN     256
#define HID     128
#define GATES   512   // 4*HID, gate order i,f,g,o

// Scratch: allocation-free rule => __device__ globals.
__device__ float g_xg[(size_t)T_STEPS * BATCH * GATES];  // x@W_ih^T + b_ih + b_hh

// ---------------- packed f32x2 helpers (FFMA2: 2 MACs/instr) ----------------
__device__ __forceinline__ unsigned long long dup2(float x) {
    unsigned long long r; asm("mov.b64 %0, {%1, %1};" : "=l"(r) : "f"(x)); return r;
}
__device__ __forceinline__ void up2(unsigned long long v, float& lo, float& hi) {
    asm("mov.b64 {%0, %1}, %2;" : "=f"(lo), "=f"(hi) : "l"(v));
}
__device__ __forceinline__ unsigned long long fma2(unsigned long long a, unsigned long long b,
                                                   unsigned long long c) {
    unsigned long long d;
    asm("fma.rn.f32x2 %0, %1, %2, %3;" : "=l"(d) : "l"(a), "l"(b), "l"(c));
    return d;
}
__device__ __forceinline__ float sigm_f(float x) { return 1.0f / (1.0f + __expf(-x)); }
__device__ __forceinline__ float tanh_f(float x) { return 2.0f / (1.0f + __expf(-2.0f * x)) - 1.0f; }

// ============================================================================
// Kernel 1: x_gates GEMM.  C[131072,512] = X[131072,256] @ Wih^T + (b_ih+b_hh)
// (unchanged from R11 baseline: measured ~570us, ~88% of f32x2 roofline)
// ============================================================================
__global__ void __launch_bounds__(256) xg_gemm(const float* __restrict__ X,
                                               const float* __restrict__ Wih,
                                               const float* __restrict__ bih,
                                               const float* __restrict__ bhh)
{
    __shared__ __align__(16) float As[2][16][132];   // [buf][k][m], padded
    __shared__ __align__(16) float Bs[2][16][132];   // [buf][k][n], padded

    const int tid = threadIdx.x;
    const int m0  = blockIdx.y * 128;
    const int n0  = blockIdx.x * 128;
    const int tx  = tid & 15;          // n micro-tile id
    const int ty  = tid >> 4;          // m micro-tile id
    const int row = tid >> 2;          // 0..63 (load role)
    const int kq  = tid & 3;

    const float* Ap = X   + (size_t)(m0 + row) * DIN + kq * 4;
    const float* Bp = Wih + (size_t)(n0 + row) * DIN + kq * 4;

    float4 ra0 = *(const float4*)(Ap);
    float4 ra1 = *(const float4*)(Ap + 64 * DIN);
    float4 rb0 = *(const float4*)(Bp);
    float4 rb1 = *(const float4*)(Bp + 64 * DIN);

    unsigned long long acc[8][4];
#pragma unroll
    for (int i = 0; i < 8; ++i)
#pragma unroll
        for (int j = 0; j < 4; ++j) acc[i][j] = 0ULL;

    int buf = 0;
#pragma unroll 1
    for (int kt = 0; kt < 16; ++kt) {
#pragma unroll
        for (int e = 0; e < 4; ++e) {
            As[buf][kq*4+e][row]    = ((const float*)&ra0)[e];
            As[buf][kq*4+e][row+64] = ((const float*)&ra1)[e];
            Bs[buf][kq*4+e][row]    = ((const float*)&rb0)[e];
            Bs[buf][kq*4+e][row+64] = ((const float*)&rb1)[e];
        }
        __syncthreads();
        if (kt < 15) {
            ra0 = *(const float4*)(Ap + (kt+1)*16);
            ra1 = *(const float4*)(Ap + 64*DIN + (kt+1)*16);
            rb0 = *(const float4*)(Bp + (kt+1)*16);
            rb1 = *(const float4*)(Bp + 64*DIN + (kt+1)*16);
        }
#pragma unroll
        for (int k = 0; k < 16; ++k) {
            float4 a0 = *(const float4*)&As[buf][k][ty*4];
            float4 a1 = *(const float4*)&As[buf][k][64 + ty*4];
            ulonglong2 b0 = *(const ulonglong2*)&Bs[buf][k][tx*4];
            ulonglong2 b1 = *(const ulonglong2*)&Bs[buf][k][64 + tx*4];
            float am[8] = {a0.x,a0.y,a0.z,a0.w,a1.x,a1.y,a1.z,a1.w};
            unsigned long long bp[4] = {b0.x, b0.y, b1.x, b1.y};
#pragma unroll
            for (int i = 0; i < 8; ++i) {
                unsigned long long ad = dup2(am[i]);
#pragma unroll
                for (int j = 0; j < 4; ++j) acc[i][j] = fma2(ad, bp[j], acc[i][j]);
            }
        }
        buf ^= 1;
    }

    float b_lo[4], b_hi[4];
#pragma unroll
    for (int j = 0; j < 4; ++j) {
        b_lo[j] = bih[n0 + tx*4 + j]      + bhh[n0 + tx*4 + j];
        b_hi[j] = bih[n0 + 64 + tx*4 + j] + bhh[n0 + 64 + tx*4 + j];
    }
#pragma unroll
    for (int i = 0; i < 8; ++i) {
        int m = m0 + ((i < 4) ? (ty*4 + i) : (64 + ty*4 + i - 4));
        float v[8];
        up2(acc[i][0], v[0], v[1]);
        up2(acc[i][1], v[2], v[3]);
        up2(acc[i][2], v[4], v[5]);
        up2(acc[i][3], v[6], v[7]);
        float* dst = g_xg + (size_t)m * GATES + n0;
        *(float4*)(dst + tx*4)      = make_float4(v[0]+b_lo[0], v[1]+b_lo[1], v[2]+b_lo[2], v[3]+b_lo[3]);
        *(float4*)(dst + 64 + tx*4) = make_float4(v[4]+b_hi[0], v[5]+b_hi[1], v[6]+b_hi[2], v[7]+b_hi[3]);
    }
}

// ============================================================================
// Kernel 2 (REWRITTEN): LSTM recurrence with REGISTER-RESIDENT W_hh.
// 64 clusters x 2 CTAs x 512 threads. Thread (q,jj,kh) holds 64 W floats in
// 32 u64 regs for all 512 steps. Per step: broadcast h LDS (jj-invariant
// addresses; kh groups offset +4 banks), 4-batch fma2, partials to smem,
// 256 update threads do gates + c/h, DSMEM h-exchange + cluster barrier.
// h layout slot(k) = k + (k>>6)*4 within stride-136 rows: kh=1 reads start
// at word 68 -> 16B-aligned (68%4==0) and bank-disjoint from kh=0 (68%32==4).
// ============================================================================
#define HSTR 136

__global__ void __launch_bounds__(512) __cluster_dims__(2, 1, 1)
lstm_rec(const float* __restrict__ Whh, const float* __restrict__ h0,
         const float* __restrict__ c0,  const float* __restrict__ fcw,
         const float* __restrict__ fcb, float* __restrict__ out)
{
    __shared__ __align__(16) float hb[2 * 4 * HSTR];   // [parity][b][HSTR]
    __shared__ __align__(16) float pre[4 * 64 * 2 * 4]; // word = tid*4 + b

    const int tid = threadIdx.x;
    const int q   = tid >> 7;          // gate 0..3
    const int jj  = (tid >> 1) & 63;   // output within slice
    const int kh  = tid & 1;           // k half
    uint32_t rank;
    asm("mov.u32 %0, %%cluster_ctarank;" : "=r"(rank));
    const uint32_t peer = rank ^ 1u;
    const int bbase = (blockIdx.x >> 1) * 4;

    // Resident W: this thread's (gate row, k-half) -> 32 u64 registers.
    unsigned long long Wp[32];
    {
        const float* wr = Whh + (size_t)(q * 128 + (int)rank * 64 + jj) * HID + kh * 64;
#pragma unroll
        for (int i = 0; i < 16; ++i) {
            ulonglong2 v = *(const ulonglong2*)(wr + i * 4);
            Wp[2*i]   = v.x;
            Wp[2*i+1] = v.y;
        }
    }

    // init h (parity 0), slot-mapped
    for (int idx = tid; idx < 4 * HID; idx += 512) {
        int b_ = idx >> 7, k = idx & 127;
        hb[b_ * HSTR + k + ((k >> 6) << 2)] = h0[(size_t)(bbase + b_) * HID + k];
    }

    // update role (tid < 256): (jj_u, b) owns c and the gate nonlinearity
    const int ujj = tid >> 2, ub = tid & 3;
    const int ujg = (int)rank * 64 + ujj;
    float c = 0.0f;
    const float* xgp = nullptr;
    float nx0 = 0.f, nx1 = 0.f, nx2 = 0.f, nx3 = 0.f;
    if (tid < 256) {
        c = c0[(size_t)(bbase + ub) * HID + ujg];
        xgp = g_xg + (size_t)(bbase + ub) * GATES + ujg;
        nx0 = xgp[0]; nx1 = xgp[128]; nx2 = xgp[256]; nx3 = xgp[384];
    }
    __syncthreads();
    asm volatile("barrier.cluster.arrive.aligned;" ::: "memory");
    asm volatile("barrier.cluster.wait.aligned;"   ::: "memory");

    int p = 0;
#pragma unroll 1
    for (int t = 0; t < T_STEPS; ++t) {
        // GEMV partials for 4 batches over this thread's 64-k half.
        const float* hp = hb + (size_t)p * 4 * HSTR + kh * 68;
        unsigned long long ae0=0,ao0=0,ae1=0,ao1=0,ae2=0,ao2=0,ae3=0,ao3=0;
#pragma unroll
        for (int i = 0; i < 16; ++i) {
            ulonglong2 hv0 = *(const ulonglong2*)(hp + 0*HSTR + i*4);
            ulonglong2 hv1 = *(const ulonglong2*)(hp + 1*HSTR + i*4);
            ulonglong2 hv2 = *(const ulonglong2*)(hp + 2*HSTR + i*4);
            ulonglong2 hv3 = *(const ulonglong2*)(hp + 3*HSTR + i*4);
            ae0 = fma2(Wp[2*i], hv0.x, ae0); ao0 = fma2(Wp[2*i+1], hv0.y, ao0);
            ae1 = fma2(Wp[2*i], hv1.x, ae1); ao1 = fma2(Wp[2*i+1], hv1.y, ao1);
            ae2 = fma2(Wp[2*i], hv2.x, ae2); ao2 = fma2(Wp[2*i+1], hv2.y, ao2);
            ae3 = fma2(Wp[2*i], hv3.x, ae3); ao3 = fma2(Wp[2*i+1], hv3.y, ao3);
        }
        float4 pv;
        { float l,h,l2,h2; up2(ae0,l,h); up2(ao0,l2,h2); pv.x = (l+h)+(l2+h2); }
        { float l,h,l2,h2; up2(ae1,l,h); up2(ao1,l2,h2); pv.y = (l+h)+(l2+h2); }
        { float l,h,l2,h2; up2(ae2,l,h); up2(ao2,l2,h2); pv.z = (l+h)+(l2+h2); }
        { float l,h,l2,h2; up2(ae3,l,h); up2(ao3,l2,h2); pv.w = (l+h)+(l2+h2); }
        *(float4*)(pre + tid * 4) = pv;
        __syncthreads();

        if (tid < 256) {
            const float* pr = pre + ujj * 8 + ub;      // word q*512 + jj*8 + kh*4 + b
            float s0 = pr[0]    + pr[4];
            float s1 = pr[512]  + pr[516];
            float s2 = pr[1024] + pr[1028];
            float s3 = pr[1536] + pr[1540];
            float gi = nx0 + s0, gf = nx1 + s1, gg = nx2 + s2, go = nx3 + s3;
            if (t + 1 < T_STEPS) {                     // prefetch next step's xg
                const float* pn = xgp + (size_t)(t + 1) * (BATCH * GATES);
                nx0 = pn[0]; nx1 = pn[128]; nx2 = pn[256]; nx3 = pn[384];
            }
            float ig = sigm_f(gi), fg = sigm_f(gf), gt = tanh_f(gg), og = sigm_f(go);
            c = fg * c + ig * gt;
            float h = og * tanh_f(c);

            int slot = ujg + ((ujg >> 6) << 2);
            float* dst = hb + ((size_t)(p ^ 1) * 4 + ub) * HSTR + slot;
            *dst = h;
            uint32_t la = (uint32_t)__cvta_generic_to_shared(dst);
            uint32_t ra;
            asm volatile("mapa.shared::cluster.u32 %0, %1, %2;" : "=r"(ra) : "r"(la), "r"(peer));
            asm volatile("st.shared::cluster.f32 [%0], %1;" :: "r"(ra), "f"(h) : "memory");
        }
        asm volatile("barrier.cluster.arrive.aligned;" ::: "memory");
        asm volatile("barrier.cluster.wait.aligned;"   ::: "memory");
        p ^= 1;
    }

    // FC head: rank 0, warp 0 — warp-parallel dots over slot-mapped final h.
    if (rank == 0 && tid < 32) {
        for (int b_ = 0; b_ < 4; ++b_) {
            const float* hr = hb + ((size_t)p * 4 + b_) * HSTR;
            float acc = 0.0f;
#pragma unroll
            for (int kk = 0; kk < 4; ++kk) {
                int k = tid + kk * 32;
                acc += hr[k + ((k >> 6) << 2)] * fcw[k];
            }
#pragma unroll
            for (int off = 16; off > 0; off >>= 1)
                acc += __shfl_xor_sync(0xFFFFFFFFu, acc, off);
            if (tid == 0) out[bbase + b_] = acc + fcb[0];
        }
    }
}

// ============================================================================
extern "C" void kernel_launch(void* const* d_in, const int* in_sizes, int n_in,
                              void* d_out, int out_size) {
    const float* x   = (const float*)d_in[0];
    const float* h0  = (const float*)d_in[1];
    const float* c0  = (const float*)d_in[2];
    const float* Wih = (const float*)d_in[3];
    const float* Whh = (const float*)d_in[4];
    const float* bih = (const float*)d_in[5];
    const float* bhh = (const float*)d_in[6];
    const float* fcw = (const float*)d_in[7];
    const float* fcb = (const float*)d_in[8];
    float* out = (float*)d_out;
    (void)in_sizes; (void)n_in; (void)out_size;

    dim3 g1(GATES / 128, (T_STEPS * BATCH) / 128);   // (4, 1024)
    xg_gemm<<<g1, 256>>>(x, Wih, bih, bhh);
    lstm_rec<<<128, 512>>>(Whh, h0, c0, fcw, fcb, out);
}